// round 3
// baseline (speedup 1.0000x reference)
#include <cuda_runtime.h>
#include <cstdint>

// ---------------- problem constants ----------------
#define B_        2
#define A_        120000
#define C_        80
#define CAP       2048      // per-class candidate buffer (expected ~1140 at T0)
#define KPRE      500
#define MAXDET    300
#define CHUNK     250       // a-values per scatter block; 120000 = 480*250
#define T0        0.99f     // initial collection threshold (fallback if out of range)
#define SCORE_THR 0.05f
#define NMS_THR   0.5f
#define MIN_SIZE  0.01f
#define BBOX_CLAMP 4.135166556742356f   // log(1000/16)
#define T3        512       // threads in select/nms kernel

// ---------------- scratch (static device globals; no allocation) ----------------
__device__ float4             g_boxes[B_ * A_];          // clipped decoded boxes
__device__ unsigned char      g_valid[B_ * A_];          // size-validity flags
__device__ unsigned long long g_cand[B_ * C_ * CAP];     // per-class candidate keys
__device__ int                g_cnt[B_ * C_];            // per-class pass-count (can exceed CAP)

// read a scalar dim that might arrive as int32 or float32 bits
__device__ __forceinline__ float read_dim(const int* p, float dflt) {
    if (!p) return dflt;
    int v = *p;
    if (v > 0 && v < 1000000) return (float)v;   // plausible int
    return __int_as_float(v);                     // else it was float bits
}

// ---------------- K0: zero counters ----------------
__global__ void k_zero() {
    int t = threadIdx.x;
    if (t < B_ * C_) g_cnt[t] = 0;
}

// ---------------- K1: fused decode + candidate scatter ----------------
// grid (480, B_), block 256. Each block: decode CHUNK anchors, then scan the
// contiguous [CHUNK x 80] score tile and push (score>T0 && valid) candidates.
__global__ void k_decode_scatter(const float* __restrict__ deltas,
                                 const float* __restrict__ scores,
                                 const float* __restrict__ anchors,
                                 const int* ph, const int* pw) {
    __shared__ unsigned char s_valid[CHUNK];
    const int b  = blockIdx.y;
    const int a0 = blockIdx.x * CHUNK;
    const int t  = threadIdx.x;

    const float W = read_dim(pw, 960.0f);
    const float H = read_dim(ph, 600.0f);

    if (t < CHUNK) {
        int a  = a0 + t;
        int gi = b * A_ + a;
        float4 d  = ((const float4*)deltas)[gi];
        float4 an = ((const float4*)anchors)[gi];
        float aw  = an.z - an.x;
        float ah  = an.w - an.y;
        float acx = an.x + 0.5f * aw;
        float acy = an.y + 0.5f * ah;
        float dw  = fminf(d.z, BBOX_CLAMP);
        float dh  = fminf(d.w, BBOX_CLAMP);
        float pcx = d.x * aw + acx;
        float pcy = d.y * ah + acy;
        float pwd = expf(dw) * aw;
        float phd = expf(dh) * ah;
        float x1 = pcx - 0.5f * pwd;
        float y1 = pcy - 0.5f * phd;
        float x2 = pcx + 0.5f * pwd;
        float y2 = pcy + 0.5f * phd;
        x1 = fminf(fmaxf(x1, 0.0f), W);
        y1 = fminf(fmaxf(y1, 0.0f), H);
        x2 = fminf(fmaxf(x2, 0.0f), W);
        y2 = fminf(fmaxf(y2, 0.0f), H);
        g_boxes[gi] = make_float4(x1, y1, x2, y2);
        unsigned char v = (((x2 - x1) >= MIN_SIZE) && ((y2 - y1) >= MIN_SIZE)) ? 1 : 0;
        g_valid[gi] = v;
        s_valid[t]  = v;
    }
    __syncthreads();

    const float* sc = scores + ((size_t)b * A_ + a0) * C_;
    const int total = CHUNK * C_;     // 20000
    int e  = t;
    int al = t / C_;
    int c  = t - al * C_;
    for (; e < total; e += 256) {
        float s = sc[e];
        if (s > T0 && s_valid[al]) {
            int a = a0 + al;
            unsigned long long key =
                (((unsigned long long)__float_as_uint(s)) << 32) |
                (unsigned long long)(0xFFFFFFFFu - (unsigned)a);
            int cls = b * C_ + c;
            int pos = atomicAdd(&g_cnt[cls], 1);
            if (pos < CAP) g_cand[(size_t)cls * CAP + pos] = key;
        }
        // advance (al,c) by 256 = 3*80 + 16
        al += 3; c += 16;
        if (c >= C_) { c -= C_; al += 1; }
    }
}

// ---------------- K2: per-class sort + NMS + output ----------------
// grid 160, block 512.
__global__ void __launch_bounds__(T3)
k_select_nms(const float* __restrict__ scores, float* __restrict__ out) {
    const int cls = blockIdx.x;
    const int b   = cls / C_;
    const int c   = cls - b * C_;
    const int tid = threadIdx.x;

    __shared__ unsigned long long s_key[CAP];
    __shared__ float s_x1[KPRE], s_y1[KPRE], s_x2[KPRE], s_y2[KPRE];
    __shared__ float s_area[KPRE], s_sc[KPRE];
    __shared__ unsigned char s_keep[KPRE];
    __shared__ int s_cnt;
    __shared__ int s_warp[T3 / 32];

    const int cnt = g_cnt[cls];
    int ncand;

    if (cnt >= KPRE && cnt <= CAP) {
        // ---- fast path: candidates already collected globally ----
        ncand = cnt;
        for (int i = tid; i < CAP; i += T3)
            s_key[i] = (i < ncand) ? g_cand[(size_t)cls * CAP + i] : 0ULL;
    } else {
        // ---- fallback: bisect threshold on float-bit integers ----
        unsigned lo = __float_as_uint(SCORE_THR);
        unsigned hi = 0x7F7FFFFFu;                 // FLT_MAX
        unsigned chosen = lo;
        for (int it = 0; it < 48; ++it) {
            unsigned mid = lo + ((hi - lo) >> 1);
            float T = __uint_as_float(mid);
            int lc = 0;
            for (int a = tid; a < A_; a += T3) {
                float s = scores[((size_t)b * A_ + a) * C_ + c];
                lc += (g_valid[b * A_ + a] && (s > T)) ? 1 : 0;
            }
            #pragma unroll
            for (int o = 16; o; o >>= 1) lc += __shfl_down_sync(0xFFFFFFFFu, lc, o);
            __syncthreads();
            if (tid == 0) s_cnt = 0;
            __syncthreads();
            if ((tid & 31) == 0) atomicAdd(&s_cnt, lc);
            __syncthreads();
            int totalc = s_cnt;
            if (totalc >= KPRE && totalc <= CAP) { chosen = mid; break; }
            if (totalc > CAP) lo = mid; else hi = mid;
            if (hi - lo <= 1) { chosen = lo; break; }
        }
        __syncthreads();
        if (tid == 0) s_cnt = 0;
        __syncthreads();
        {
            float T = __uint_as_float(chosen);
            for (int a = tid; a < A_; a += T3) {
                float s = scores[((size_t)b * A_ + a) * C_ + c];
                if (g_valid[b * A_ + a] && s > T) {
                    int pos = atomicAdd(&s_cnt, 1);
                    if (pos < CAP)
                        s_key[pos] =
                            (((unsigned long long)__float_as_uint(s)) << 32) |
                            (unsigned long long)(0xFFFFFFFFu - (unsigned)a);
                }
            }
        }
        __syncthreads();
        ncand = min(s_cnt, CAP);
        for (int i = tid; i < CAP; i += T3)
            if (i >= ncand) s_key[i] = 0ULL;
    }
    __syncthreads();

    // ---- bitonic sort descending (CAP = 2048 keys, key 0 = padding) ----
    for (int size2 = 2; size2 <= CAP; size2 <<= 1) {
        for (int stride = size2 >> 1; stride > 0; stride >>= 1) {
            __syncthreads();
            for (int t2 = tid; t2 < CAP / 2; t2 += T3) {
                int i1 = 2 * t2 - (t2 & (stride - 1));
                int i2 = i1 + stride;
                unsigned long long va = s_key[i1];
                unsigned long long vb = s_key[i2];
                bool descBlock = ((i1 & size2) == 0);
                bool sw = descBlock ? (va < vb) : (va > vb);
                if (sw) { s_key[i1] = vb; s_key[i2] = va; }
            }
        }
    }
    __syncthreads();

    // ---- extract top-500: boxes, areas, scores ----
    if (tid < KPRE) {
        unsigned long long k = s_key[tid];
        if (k != 0ULL) {
            unsigned a = 0xFFFFFFFFu - (unsigned)(k & 0xFFFFFFFFu);
            float4 bx = g_boxes[b * A_ + (int)a];
            s_x1[tid] = bx.x; s_y1[tid] = bx.y;
            s_x2[tid] = bx.z; s_y2[tid] = bx.w;
            s_area[tid] = (bx.z - bx.x) * (bx.w - bx.y);
            s_sc[tid]  = __uint_as_float((unsigned)(k >> 32));
            s_keep[tid] = 1;
        } else {
            s_x1[tid] = 0.f; s_y1[tid] = 0.f; s_x2[tid] = 0.f; s_y2[tid] = 0.f;
            s_area[tid] = 0.f; s_sc[tid] = -1.0f;
            s_keep[tid] = 0;
        }
    }
    __syncthreads();

    // register copy of "my" box (thread tid owns detection j = tid)
    float jx1 = 0.f, jy1 = 0.f, jx2 = 0.f, jy2 = 0.f, jarea = 0.f;
    int jkeep = 0;
    if (tid < KPRE) {
        jx1 = s_x1[tid]; jy1 = s_y1[tid];
        jx2 = s_x2[tid]; jy2 = s_y2[tid];
        jarea = s_area[tid];
        jkeep = s_keep[tid];
    }

    // ---- serial greedy NMS; barrier only after iterations that wrote ----
    bool dirty = false;
    for (int i = 0; i < KPRE; ++i) {
        if (dirty) __syncthreads();
        bool ki = (s_keep[i] != 0);     // uniform across block
        dirty = ki;
        if (ki) {
            float ix1 = s_x1[i], iy1 = s_y1[i];
            float ix2 = s_x2[i], iy2 = s_y2[i];
            float iar = s_area[i];
            int j = tid;
            if (j > i && j < KPRE && jkeep) {
                float ltx = fmaxf(ix1, jx1);
                float lty = fmaxf(iy1, jy1);
                float rbx = fminf(ix2, jx2);
                float rby = fminf(iy2, jy2);
                float w = fmaxf(rbx - ltx, 0.0f);
                float h = fmaxf(rby - lty, 0.0f);
                float inter = w * h;
                float denom = fmaxf(iar + jarea - inter, 1e-9f);
                float iou = __fdiv_rn(inter, denom);   // IEEE div, matches ref math
                if (iou > NMS_THR) { jkeep = 0; s_keep[j] = 0; }
            }
        }
    }
    __syncthreads();

    // ---- compact kept detections in score order, write output ----
    int k = (tid < KPRE) ? (s_keep[tid] ? 1 : 0) : 0;
    unsigned ballot = __ballot_sync(0xFFFFFFFFu, k);
    int lane = tid & 31;
    int wid  = tid >> 5;
    int inwarp = __popc(ballot & ((1u << lane) - 1u));
    if (lane == 0) s_warp[wid] = __popc(ballot);
    __syncthreads();
    int off = 0;
    #pragma unroll
    for (int w = 0; w < T3 / 32; ++w) {
        int v = s_warp[w];
        if (w < wid) off += v;
    }
    int total = 0;
    #pragma unroll
    for (int w = 0; w < T3 / 32; ++w) total += s_warp[w];
    int rank = off + inwarp;

    float* orow = out + (size_t)cls * MAXDET * 5;
    if (k && rank < MAXDET) {
        float* p = orow + (size_t)rank * 5;
        p[0] = jx1; p[1] = jy1; p[2] = jx2; p[3] = jy2;
        p[4] = s_sc[tid];
    }
    int nk = min(total, MAXDET);
    for (int r = nk + tid; r < MAXDET; r += T3) {
        float* p = orow + (size_t)r * 5;
        p[0] = 0.0f; p[1] = 0.0f; p[2] = 0.0f; p[3] = 0.0f; p[4] = -1.0f;
    }
}

// ---------------- launcher ----------------
extern "C" void kernel_launch(void* const* d_in, const int* in_sizes, int n_in,
                              void* d_out, int out_size) {
    const float* deltas  = (const float*)d_in[0];
    const float* scores  = (const float*)d_in[1];
    const float* anchors = (const float*)d_in[2];
    const int*   ph = (n_in > 3) ? (const int*)d_in[3] : nullptr;
    const int*   pw = (n_in > 4) ? (const int*)d_in[4] : nullptr;

    k_zero<<<1, 256>>>();
    dim3 g1(A_ / CHUNK, B_);           // (480, 2)
    k_decode_scatter<<<g1, 256>>>(deltas, scores, anchors, ph, pw);
    k_select_nms<<<B_ * C_, T3>>>(scores, (float*)d_out);
}

// round 8
// speedup vs baseline: 1.4378x; 1.4378x over previous
#include <cuda_runtime.h>
#include <cstdint>

// ---------------- problem constants ----------------
#define B_        2
#define A_        120000
#define C_        80
#define CAP       1024      // per-class candidate buffer (expected ~780 at T0)
#define KPRE      500
#define KPAD      512       // padded box-array size (matrix lanes may touch [KPRE,512))
#define MAXDET    300
#define CHUNK     250       // a-values per scatter block; 120000 = 480*250
#define T0        0.993f    // collection threshold (fallback if count outside [KPRE,CAP])
#define SCORE_THR 0.05f
#define NMS_THR   0.5f
#define MIN_SIZE  0.01f
#define BBOX_CLAMP 4.135166556742356f   // log(1000/16)
#define T3        512       // threads in select/nms kernel

// ---------------- scratch (static device globals; no allocation) ----------------
__device__ float4             g_boxes[B_ * A_];          // clipped decoded boxes
__device__ unsigned char      g_valid[B_ * A_];          // size-validity flags
__device__ unsigned long long g_cand[B_ * C_ * CAP];     // per-class candidate keys
__device__ int                g_cnt[B_ * C_];            // per-class pass-count (can exceed CAP)

// read a scalar dim that might arrive as int32 or float32 bits
__device__ __forceinline__ float read_dim(const int* p, float dflt) {
    if (!p) return dflt;
    int v = *p;
    if (v > 0 && v < 1000000) return (float)v;   // plausible int
    return __int_as_float(v);                     // else it was float bits
}

// ---------------- K0: zero counters ----------------
__global__ void k_zero() {
    int t = threadIdx.x;
    if (t < B_ * C_) g_cnt[t] = 0;
}

// ---------------- K1: fused decode + candidate scatter ----------------
// grid (480, B_), block 256. Decode CHUNK anchors, then scan the contiguous
// [CHUNK x 80] score tile via float4 loads and push (score>T0 && valid)
// candidates into the per-class global buffer.
__global__ void k_decode_scatter(const float* __restrict__ deltas,
                                 const float* __restrict__ scores,
                                 const float* __restrict__ anchors,
                                 const int* ph, const int* pw) {
    __shared__ unsigned char s_valid[CHUNK];
    const int b  = blockIdx.y;
    const int a0 = blockIdx.x * CHUNK;
    const int t  = threadIdx.x;

    const float W = read_dim(pw, 960.0f);
    const float H = read_dim(ph, 600.0f);

    if (t < CHUNK) {
        int a  = a0 + t;
        int gi = b * A_ + a;
        float4 d  = ((const float4*)deltas)[gi];
        float4 an = ((const float4*)anchors)[gi];
        float aw  = an.z - an.x;
        float ah  = an.w - an.y;
        float acx = an.x + 0.5f * aw;
        float acy = an.y + 0.5f * ah;
        float dw  = fminf(d.z, BBOX_CLAMP);
        float dh  = fminf(d.w, BBOX_CLAMP);
        float pcx = d.x * aw + acx;
        float pcy = d.y * ah + acy;
        float pwd = expf(dw) * aw;
        float phd = expf(dh) * ah;
        float x1 = pcx - 0.5f * pwd;
        float y1 = pcy - 0.5f * phd;
        float x2 = pcx + 0.5f * pwd;
        float y2 = pcy + 0.5f * phd;
        x1 = fminf(fmaxf(x1, 0.0f), W);
        y1 = fminf(fmaxf(y1, 0.0f), H);
        x2 = fminf(fmaxf(x2, 0.0f), W);
        y2 = fminf(fmaxf(y2, 0.0f), H);
        g_boxes[gi] = make_float4(x1, y1, x2, y2);
        unsigned char v = (((x2 - x1) >= MIN_SIZE) && ((y2 - y1) >= MIN_SIZE)) ? 1 : 0;
        g_valid[gi] = v;
        s_valid[t]  = v;
    }
    __syncthreads();

    // score tile: CHUNK*80 = 20000 floats = 5000 float4 (80 % 4 == 0 so each
    // float4 stays inside one anchor row: a = 4q/80, c0 = 4q%80)
    const float4* sc4 = (const float4*)(scores + ((size_t)b * A_ + a0) * C_);
    const int nq = CHUNK * C_ / 4;     // 5000
    for (int q = t; q < nq; q += 256) {
        float4 v = sc4[q];
        int al = q / (C_ / 4);
        if (!s_valid[al]) continue;
        if (v.x > T0 || v.y > T0 || v.z > T0 || v.w > T0) {
            int c0 = (q - al * (C_ / 4)) * 4;
            int a  = a0 + al;
            unsigned lowkey = 0xFFFFFFFFu - (unsigned)a;
            float comp[4] = {v.x, v.y, v.z, v.w};
            #pragma unroll
            for (int j = 0; j < 4; ++j) {
                float s = comp[j];
                if (s > T0) {
                    unsigned long long key =
                        (((unsigned long long)__float_as_uint(s)) << 32) |
                        (unsigned long long)lowkey;
                    int cls = b * C_ + c0 + j;
                    int pos = atomicAdd(&g_cnt[cls], 1);
                    if (pos < CAP) g_cand[(size_t)cls * CAP + pos] = key;
                }
            }
        }
    }
}

// ---------------- K2: per-class sort + matrix-NMS + output ----------------
// grid 160, block 512.
__global__ void __launch_bounds__(T3)
k_select_nms(const float* __restrict__ scores, float* __restrict__ out) {
    const int cls  = blockIdx.x;
    const int b    = cls / C_;
    const int c    = cls - b * C_;
    const int tid  = threadIdx.x;
    const int lane = tid & 31;
    const int wid  = tid >> 5;

    // 32KB buffer: first phase = sort keys (u64[1024]); second phase =
    // transposed suppression matrix supT[w*512 + j] (16*512 u32)
    __shared__ unsigned long long s_buf64[4096];
    unsigned long long* s_key  = s_buf64;
    unsigned*           s_supT = (unsigned*)s_buf64;

    __shared__ float s_x1[KPAD], s_y1[KPAD], s_x2[KPAD], s_y2[KPAD];
    __shared__ float s_area[KPAD], s_sc[KPAD];
    __shared__ unsigned s_kw[16], s_nw[16];
    __shared__ int s_cnt, s_changed;
    __shared__ int s_warp[T3 / 32];

    const int cnt = g_cnt[cls];
    int ncand;

    if (cnt >= KPRE && cnt <= CAP) {
        // ---- fast path: candidates already collected globally ----
        ncand = cnt;
        for (int i = tid; i < CAP; i += T3)
            s_key[i] = (i < ncand) ? g_cand[(size_t)cls * CAP + i] : 0ULL;
    } else {
        // ---- fallback: bisect threshold on float-bit integers ----
        unsigned lo = __float_as_uint(SCORE_THR);
        unsigned hi = 0x7F7FFFFFu;                 // FLT_MAX
        unsigned chosen = lo;
        for (int it = 0; it < 48; ++it) {
            unsigned mid = lo + ((hi - lo) >> 1);
            float T = __uint_as_float(mid);
            int lc = 0;
            for (int a = tid; a < A_; a += T3) {
                float s = scores[((size_t)b * A_ + a) * C_ + c];
                lc += (g_valid[b * A_ + a] && (s > T)) ? 1 : 0;
            }
            #pragma unroll
            for (int o = 16; o; o >>= 1) lc += __shfl_down_sync(0xFFFFFFFFu, lc, o);
            __syncthreads();
            if (tid == 0) s_cnt = 0;
            __syncthreads();
            if ((tid & 31) == 0) atomicAdd(&s_cnt, lc);
            __syncthreads();
            int totalc = s_cnt;
            if (totalc >= KPRE && totalc <= CAP) { chosen = mid; break; }
            if (totalc > CAP) lo = mid; else hi = mid;
            if (hi - lo <= 1) { chosen = lo; break; }
        }
        __syncthreads();
        if (tid == 0) s_cnt = 0;
        __syncthreads();
        {
            float T = __uint_as_float(chosen);
            for (int a = tid; a < A_; a += T3) {
                float s = scores[((size_t)b * A_ + a) * C_ + c];
                if (g_valid[b * A_ + a] && s > T) {
                    int pos = atomicAdd(&s_cnt, 1);
                    if (pos < CAP)
                        s_key[pos] =
                            (((unsigned long long)__float_as_uint(s)) << 32) |
                            (unsigned long long)(0xFFFFFFFFu - (unsigned)a);
                }
            }
        }
        __syncthreads();
        ncand = min(s_cnt, CAP);
        for (int i = tid; i < CAP; i += T3)
            if (i >= ncand) s_key[i] = 0ULL;
    }
    __syncthreads();

    // ---- bitonic sort descending (CAP = 1024; exactly one pair per thread) ----
    for (int size2 = 2; size2 <= CAP; size2 <<= 1) {
        for (int stride = size2 >> 1; stride > 0; stride >>= 1) {
            __syncthreads();
            int i1 = 2 * tid - (tid & (stride - 1));
            int i2 = i1 + stride;
            unsigned long long va = s_key[i1];
            unsigned long long vb = s_key[i2];
            bool descBlock = ((i1 & size2) == 0);
            bool sw = descBlock ? (va < vb) : (va > vb);
            if (sw) { s_key[i1] = vb; s_key[i2] = va; }
        }
    }
    __syncthreads();

    // ---- extract top-500 boxes (padding beyond KPRE zeroed for matrix lanes) ----
    float jx1 = 0.f, jy1 = 0.f, jx2 = 0.f, jy2 = 0.f;
    float jsc = -1.0f;
    {
        unsigned long long k = (tid < KPRE) ? s_key[tid] : 0ULL;
        if (k != 0ULL) {
            unsigned a = 0xFFFFFFFFu - (unsigned)(k & 0xFFFFFFFFu);
            float4 bx = g_boxes[b * A_ + (int)a];
            jx1 = bx.x; jy1 = bx.y; jx2 = bx.z; jy2 = bx.w;
            jsc = __uint_as_float((unsigned)(k >> 32));
        }
        s_x1[tid] = jx1; s_y1[tid] = jy1;
        s_x2[tid] = jx2; s_y2[tid] = jy2;
        s_area[tid] = (jx2 - jx1) * (jy2 - jy1);
        s_sc[tid]   = jsc;
    }
    __syncthreads();   // keys fully consumed; s_buf64 now reusable as supT

    // ---- build transposed suppression bit-matrix ----
    // supT[w*512 + j] : bit l set  <=>  i = 32w+l < j  and  iou(i,j) > thr
    for (int i = tid; i < 16 * 512; i += T3) s_supT[i] = 0;
    __syncthreads();

    for (int j = wid; j < KPRE; j += 16) {
        float bx1 = s_x1[j], by1 = s_y1[j], bx2 = s_x2[j], by2 = s_y2[j];
        float bar = s_area[j];
        int nw = (j + 31) >> 5;           // words containing any i < j
        for (int w = 0; w < nw; ++w) {
            int i = (w << 5) + lane;      // i < 512 always (box arrays padded)
            float ltx = fmaxf(s_x1[i], bx1);
            float lty = fmaxf(s_y1[i], by1);
            float rbx = fminf(s_x2[i], bx2);
            float rby = fminf(s_y2[i], by2);
            float wd = fmaxf(rbx - ltx, 0.0f);
            float ht = fmaxf(rby - lty, 0.0f);
            float inter = wd * ht;
            float denom = fmaxf(s_area[i] + bar - inter, 1e-9f);
            float iou = __fdiv_rn(inter, denom);   // IEEE div, matches ref math
            unsigned m = __ballot_sync(0xFFFFFFFFu, (i < j) && (iou > NMS_THR));
            if (lane == 0) s_supT[(w << 9) + j] = m;
        }
    }

    // ---- init keep words: valid = top score above SCORE_THR ----
    const bool vme = (tid < KPRE) && (jsc > SCORE_THR);
    {
        unsigned w = __ballot_sync(0xFFFFFFFFu, vme);
        if (lane == 0) s_kw[wid] = w;
    }
    __syncthreads();

    // ---- Jacobi fixed-point sweep: keep[j] = valid[j] && !(sup-col_j & keep) ----
    // Unique fixed point == greedy NMS; converges in <= chain-depth passes.
    bool alive = vme;
    for (int pass = 0; pass < KPRE + 1; ++pass) {
        unsigned sup = 0;
        if (tid < KPRE) {
            #pragma unroll
            for (int w = 0; w < 16; ++w)
                sup |= s_supT[(w << 9) + tid] & s_kw[w];
        }
        alive = vme && (sup == 0);
        unsigned word = __ballot_sync(0xFFFFFFFFu, alive);
        if (lane == 0) s_nw[wid] = word;
        if (tid == 0) s_changed = 0;
        __syncthreads();
        if (tid < 16 && s_nw[tid] != s_kw[tid]) s_changed = 1;
        __syncthreads();
        if (tid < 16) s_kw[tid] = s_nw[tid];
        __syncthreads();
        if (!s_changed) break;
    }

    // ---- compact kept detections in score order, write output ----
    int k = ((s_kw[wid] >> lane) & 1u);
    unsigned ballot = __ballot_sync(0xFFFFFFFFu, k);
    int inwarp = __popc(ballot & ((1u << lane) - 1u));
    if (lane == 0) s_warp[wid] = __popc(ballot);
    __syncthreads();
    int off = 0, total = 0;
    #pragma unroll
    for (int w = 0; w < T3 / 32; ++w) {
        int v = s_warp[w];
        if (w < wid) off += v;
        total += v;
    }
    int rank = off + inwarp;

    float* orow = out + (size_t)cls * MAXDET * 5;
    if (k && rank < MAXDET) {
        float* p = orow + (size_t)rank * 5;
        p[0] = jx1; p[1] = jy1; p[2] = jx2; p[3] = jy2;
        p[4] = jsc;
    }
    int nk = min(total, MAXDET);
    for (int r = nk + tid; r < MAXDET; r += T3) {
        float* p = orow + (size_t)r * 5;
        p[0] = 0.0f; p[1] = 0.0f; p[2] = 0.0f; p[3] = 0.0f; p[4] = -1.0f;
    }
}

// ---------------- launcher ----------------
extern "C" void kernel_launch(void* const* d_in, const int* in_sizes, int n_in,
                              void* d_out, int out_size) {
    const float* deltas  = (const float*)d_in[0];
    const float* scores  = (const float*)d_in[1];
    const float* anchors = (const float*)d_in[2];
    const int*   ph = (n_in > 3) ? (const int*)d_in[3] : nullptr;
    const int*   pw = (n_in > 4) ? (const int*)d_in[4] : nullptr;

    k_zero<<<1, 256>>>();
    dim3 g1(A_ / CHUNK, B_);           // (480, 2)
    k_decode_scatter<<<g1, 256>>>(deltas, scores, anchors, ph, pw);
    k_select_nms<<<B_ * C_, T3>>>(scores, (float*)d_out);
}